// round 7
// baseline (speedup 1.0000x reference)
#include <cuda_runtime.h>
#include <cuda_fp16.h>
#include <cstdint>
#include <cstddef>

#define NN 100000
#define EE 500000
#define MROWS 200000
#define MTILES 1563  // ceil(200000/128)

// Per-node first-layer tables in fp16 (102.4 MB -> mostly L2-resident).
// P[n, 0:128] = z_pnode[n] @ w1_top ; P[n, 128:256] = z_pnode[n] @ w1_bot + b1
__device__ __half g_P[(size_t)NN * 256];
__device__ __half g_O[(size_t)NN * 256];

__device__ __forceinline__ void mma_f16(float* d, const uint32_t* a,
                                        const uint32_t* b) {
  asm volatile(
      "mma.sync.aligned.m16n8k16.row.col.f32.f16.f16.f32 "
      "{%0,%1,%2,%3}, {%4,%5,%6,%7}, {%8,%9}, {%0,%1,%2,%3};"
      : "+f"(d[0]), "+f"(d[1]), "+f"(d[2]), "+f"(d[3])
      : "r"(a[0]), "r"(a[1]), "r"(a[2]), "r"(a[3]), "r"(b[0]), "r"(b[1]));
}

__device__ __forceinline__ void cp16(void* smem_dst, const void* gmem_src) {
  uint32_t s = (uint32_t)__cvta_generic_to_shared(smem_dst);
  asm volatile("cp.async.cg.shared.global [%0], [%1], 16;" ::"r"(s),
               "l"(gmem_src));
}

__device__ __forceinline__ uint32_t pack_h2(float lo, float hi) {
  __half2 h = __floats2half2_rn(lo, hi);
  return *(uint32_t*)&h;
}

#define BS_LD2 264  // half2 per B pair-row (1056B; %128==32 -> conflict-free)
#define AS_LDF 132  // fp32 per A row (528B; words%32==4 -> conflict-free)
#define CS_LDH 264  // halves per staged C row (528B) == A row bytes
#define B_BYTES (64 * BS_LD2 * 4)           // 67584
#define A_BYTES (128 * AS_LDF * 4)          // 67584 (== 128*CS_LDH*2)
#define SMEM_TOTAL (B_BYTES + 2 * A_BYTES)  // 202752

// ---------------------------------------------------------------------------
// Fused persistent fp16 GEMM: C[200000,256] = Z @ [w1_top | w1_bot] (+b1 bot).
// 148 CTAs x 512 threads (16 warps; warp tile 32x64 of the 128x256 CTA tile).
// fp32 A double-buffered via cp.async; fp16 B resident; C staged in smem.
// ---------------------------------------------------------------------------
__global__ void __launch_bounds__(512, 1) gemm_kernel(
    const float* __restrict__ zp, const float* __restrict__ zo,
    const float* __restrict__ w1, const float* __restrict__ b1) {
  extern __shared__ char smem_raw[];
  __half2* Bsh = (__half2*)smem_raw;  // [64 pair-rows][BS_LD2]
  char* Abase = smem_raw + B_BYTES;   // 2 x (A fp32 tile | C half stage)
  const int tid = threadIdx.x;

  // A tile async load: 4096 x 16B fp32 chunks, 8 per thread.
  auto issueA = [&](int tile, int buf) {
    char* dst = Abase + buf * A_BYTES;
    int row0 = tile * 128;
#pragma unroll
    for (int j = 0; j < 8; j++) {
      int s = tid + 512 * j;
      int r = s >> 5;
      int c4 = s & 31;
      int grow = row0 + r;
      if (grow > MROWS - 1) grow = MROWS - 1;
      const float* src = (grow < NN) ? (zp + (size_t)grow * 128)
                                     : (zo + (size_t)(grow - NN) * 128);
      cp16(dst + r * (AS_LDF * 4) + c4 * 16, src + c4 * 4);
    }
  };

  int t = blockIdx.x;
  issueA(t, 0);
  asm volatile("cp.async.commit_group;" ::: "memory");

  // One-time B fill: fp32 w1 -> fp16 [pair p][nn], half2=(w1t[2p][nn],w1t[2p+1][nn])
  {
    const float4* w4 = (const float4*)w1;
#pragma unroll
    for (int j = 0; j < 8; j++) {
      int slot = tid + 512 * j;  // 4096 slots
      int c4 = slot & 31;
      int p = (slot >> 5) & 63;
      int hh = slot >> 11;  // 0: top cols, 1: bot cols
      float4 fa = w4[(2 * p + hh * 128) * 32 + c4];
      float4 fb = w4[(2 * p + 1 + hh * 128) * 32 + c4];
      uint4 v;
      v.x = pack_h2(fa.x, fb.x);
      v.y = pack_h2(fa.y, fb.y);
      v.z = pack_h2(fa.z, fb.z);
      v.w = pack_h2(fa.w, fb.w);
      *(uint4*)((char*)Bsh + p * (BS_LD2 * 4) + (hh * 128 + c4 * 4) * 4) = v;
    }
  }

  const int lane = tid & 31;
  const int wid = tid >> 5;
  const int g = lane >> 2;
  const int tg = lane & 3;
  const int wm = wid & 3;   // 4 warp-rows of 32
  const int wn = wid >> 2;  // 4 warp-cols of 64
  const int arow = wm * 32;
  const int bcol = wn * 64;
  const bool bot = (bcol >= 128);
  int buf = 0;

  while (true) {
    int tn = t + gridDim.x;
    bool more = (tn < MTILES);
    if (more) issueA(tn, buf ^ 1);
    asm volatile("cp.async.commit_group;" ::: "memory");
    asm volatile("cp.async.wait_group 1;" ::: "memory");
    __syncthreads();

    const float* A = (const float*)(Abase + buf * A_BYTES);
    float acc[2][8][4];
#pragma unroll
    for (int mi = 0; mi < 2; mi++)
#pragma unroll
      for (int ni = 0; ni < 8; ni++)
#pragma unroll
        for (int q = 0; q < 4; q++) acc[mi][ni][q] = 0.f;

#pragma unroll
    for (int k0 = 0; k0 < 128; k0 += 16) {
      int hp = k0 >> 1;
      uint32_t bf[8][2];
#pragma unroll
      for (int ni = 0; ni < 8; ni++) {
        int col = bcol + ni * 8 + g;
        bf[ni][0] = *(const uint32_t*)&Bsh[(hp + tg) * BS_LD2 + col];
        bf[ni][1] = *(const uint32_t*)&Bsh[(hp + 4 + tg) * BS_LD2 + col];
      }
#pragma unroll
      for (int mi = 0; mi < 2; mi++) {
        int rb = arow + mi * 16 + g;
        uint32_t af[4];
        {
          float2 v = *(const float2*)&A[rb * AS_LDF + k0 + 2 * tg];
          af[0] = pack_h2(v.x, v.y);
        }
        {
          float2 v = *(const float2*)&A[(rb + 8) * AS_LDF + k0 + 2 * tg];
          af[1] = pack_h2(v.x, v.y);
        }
        {
          float2 v = *(const float2*)&A[rb * AS_LDF + k0 + 8 + 2 * tg];
          af[2] = pack_h2(v.x, v.y);
        }
        {
          float2 v = *(const float2*)&A[(rb + 8) * AS_LDF + k0 + 8 + 2 * tg];
          af[3] = pack_h2(v.x, v.y);
        }
#pragma unroll
        for (int ni = 0; ni < 8; ni++) mma_f16(acc[mi][ni], af, bf[ni]);
      }
    }

    // Stage C into this A buffer (fully consumed), then coalesced row stores.
    __syncthreads();
    __half* Cs = (__half*)(Abase + buf * A_BYTES);
#pragma unroll
    for (int mi = 0; mi < 2; mi++) {
#pragma unroll
      for (int hf = 0; hf < 2; hf++) {
        int r = wm * 32 + mi * 16 + hf * 8 + g;
#pragma unroll
        for (int ni = 0; ni < 8; ni++) {
          int c = bcol + ni * 8 + tg * 2;
          float v0 = acc[mi][ni][hf * 2];
          float v1 = acc[mi][ni][hf * 2 + 1];
          if (bot) {
            float2 bb = *(const float2*)(b1 + (c - 128));
            v0 += bb.x;
            v1 += bb.y;
          }
          *(__half2*)(Cs + r * CS_LDH + c) = __floats2half2_rn(v0, v1);
        }
      }
    }
    __syncthreads();
    int row0 = t * 128;
#pragma unroll
    for (int j = 0; j < 8; j++) {
      int slot = tid + 512 * j;  // 128 rows x 32 uint4
      int r = slot >> 5;
      int c4 = slot & 31;
      int grow = row0 + r;
      if (grow < MROWS) {
        uint4 v = *(const uint4*)(Cs + r * CS_LDH + c4 * 8);
        __half* tab = (grow < NN) ? (g_P + (size_t)grow * 256)
                                  : (g_O + (size_t)(grow - NN) * 256);
        *(uint4*)(tab + c4 * 8) = v;
      }
    }
    __syncthreads();
    if (!more) break;
    t = tn;
    buf ^= 1;
  }
}

// ---------------------------------------------------------------------------
// Edge pass: persistent warps, 2 edges per warp-iteration (16-lane halves),
// half2 math, paired float2 output stores.
// out[e] = relu(tabS[src,0:128] + tabD[dst,128:256]) . w2 + b2
// ---------------------------------------------------------------------------
#define NPAIRS (3 * EE / 2)  // 750000
__global__ void __launch_bounds__(256) edge_kernel(
    const int* __restrict__ e0, const int* __restrict__ e1,
    const int* __restrict__ e2, const float* __restrict__ w2,
    const float* __restrict__ b2, float* __restrict__ out) {
  const int lane = threadIdx.x & 31;
  const int h = lane >> 4;
  const int l = lane & 15;
  const int warpId = (blockIdx.x * 256 + threadIdx.x) >> 5;
  const int W = gridDim.x * 8;

  // Per-lane second-layer weights (features l*8 .. l*8+7) in half2.
  const float4 wa = ((const float4*)w2)[l * 2];
  const float4 wb = ((const float4*)w2)[l * 2 + 1];
  const __half2 w01 = __floats2half2_rn(wa.x, wa.y);
  const __half2 w23 = __floats2half2_rn(wa.z, wa.w);
  const __half2 w45 = __floats2half2_rn(wb.x, wb.y);
  const __half2 w67 = __floats2half2_rn(wb.z, wb.w);
  const __half2 z2 = __float2half2_rn(0.f);
  const float b2v = b2[0];

#pragma unroll 4
  for (int p = warpId; p < NPAIRS; p += W) {
    int e = 2 * p + h;  // pair never straddles a type boundary (EE even)
    int t = (e >= EE) + (e >= 2 * EE);
    int ei = e - t * EE;
    const int* idx = (t == 0) ? e0 : (t == 1) ? e1 : e2;
    int s = idx[ei];
    int d = idx[EE + ei];
    const __half* srow = ((t == 0) ? g_P : g_O) + (unsigned)s * 256u;
    const __half* drow = ((t == 1) ? g_P : g_O) + (unsigned)d * 256u + 128u;

    uint4 sa = ((const uint4*)srow)[l];
    uint4 da = ((const uint4*)drow)[l];

    __half2 h0 = __hmax2(__hadd2(*(__half2*)&sa.x, *(__half2*)&da.x), z2);
    __half2 h1 = __hmax2(__hadd2(*(__half2*)&sa.y, *(__half2*)&da.y), z2);
    __half2 h2 = __hmax2(__hadd2(*(__half2*)&sa.z, *(__half2*)&da.z), z2);
    __half2 h3 = __hmax2(__hadd2(*(__half2*)&sa.w, *(__half2*)&da.w), z2);
    __half2 pa = __hfma2(h1, w23, __hmul2(h0, w01));
    __half2 pb = __hfma2(h3, w67, __hmul2(h2, w45));
    float2 fa = __half22float2(pa);
    float2 fb = __half22float2(pb);
    float acc = (fa.x + fa.y) + (fb.x + fb.y);
#pragma unroll
    for (int o = 8; o; o >>= 1) acc += __shfl_xor_sync(0xffffffffu, acc, o);
    // lane 0 holds edge 2p, lane 16 holds edge 2p+1: pack one float2 store.
    float other = __shfl_sync(0xffffffffu, acc, 16);
    if (lane == 0) {
      float2 v = make_float2(acc + b2v, other + b2v);
      *(float2*)(out + 2 * p) = v;
    }
  }
}

extern "C" void kernel_launch(void* const* d_in, const int* in_sizes, int n_in,
                              void* d_out, int out_size) {
  const float* zp = (const float*)d_in[0];
  const float* zo = (const float*)d_in[1];
  const int* e0 = (const int*)d_in[2];
  const int* e1 = (const int*)d_in[3];
  const int* e2 = (const int*)d_in[4];
  const float* w1 = (const float*)d_in[5];
  const float* b1 = (const float*)d_in[6];
  const float* w2 = (const float*)d_in[7];
  const float* b2 = (const float*)d_in[8];

  cudaFuncSetAttribute(gemm_kernel,
                       cudaFuncAttributeMaxDynamicSharedMemorySize, SMEM_TOTAL);
  gemm_kernel<<<148, 512, SMEM_TOTAL>>>(zp, zo, w1, b1);

  edge_kernel<<<148 * 8, 256>>>(e0, e1, e2, w2, b2, (float*)d_out);
}

// round 8
// speedup vs baseline: 1.2998x; 1.2998x over previous
#include <cuda_runtime.h>
#include <cuda_fp16.h>
#include <cstdint>
#include <cstddef>

#define NN 100000
#define EE 500000
#define MROWS 200000
#define MT64 3125  // 200000/64 exact

// Per-node first-layer tables in fp16 (102.4 MB -> mostly L2-resident).
// P[n, 0:128] = z_pnode[n] @ w1_top ; P[n, 128:256] = z_pnode[n] @ w1_bot + b1
__device__ __half g_P[(size_t)NN * 256];
__device__ __half g_O[(size_t)NN * 256];

__device__ __forceinline__ void mma_f16(float* d, const uint32_t* a,
                                        const uint32_t* b) {
  asm volatile(
      "mma.sync.aligned.m16n8k16.row.col.f32.f16.f16.f32 "
      "{%0,%1,%2,%3}, {%4,%5,%6,%7}, {%8,%9}, {%0,%1,%2,%3};"
      : "+f"(d[0]), "+f"(d[1]), "+f"(d[2]), "+f"(d[3])
      : "r"(a[0]), "r"(a[1]), "r"(a[2]), "r"(a[3]), "r"(b[0]), "r"(b[1]));
}

__device__ __forceinline__ void cp16(void* smem_dst, const void* gmem_src) {
  uint32_t s = (uint32_t)__cvta_generic_to_shared(smem_dst);
  asm volatile("cp.async.cg.shared.global [%0], [%1], 16;" ::"r"(s),
               "l"(gmem_src));
}

__device__ __forceinline__ uint32_t pack_h2(float lo, float hi) {
  __half2 h = __floats2half2_rn(lo, hi);
  return *(uint32_t*)&h;
}

#define BS_LD2 136  // half2 per B pair-row (544B; %128==32B -> 8tg+g banks, clean)
#define AS_LDF 132  // fp32 per A row (528B; words%32==4 -> conflict-free)
#define CS_LDH 136  // halves per staged C row (272B)
#define B_BYTES (64 * BS_LD2 * 4)           // 34816
#define A_BYTES (64 * AS_LDF * 4)           // 33792
#define SMEM_TOTAL (B_BYTES + 2 * A_BYTES)  // 102400 -> 2 CTAs/SM

// ---------------------------------------------------------------------------
// Fused persistent fp16 GEMM: C[200000,256] = Z @ [w1_top | w1_bot] (+b1 bot).
// 296 CTAs x 256 threads; CTA tile 64 x 128 (nh = blockIdx.x&1 picks N-half).
// 2 CTAs/SM -> two independent cp.async pipelines per SM hide latency.
// 8 warps, warp tile 32x32. fp32 A double-buffered; fp16 B-half resident.
// ---------------------------------------------------------------------------
__global__ void __launch_bounds__(256, 2) gemm_kernel(
    const float* __restrict__ zp, const float* __restrict__ zo,
    const float* __restrict__ w1, const float* __restrict__ b1) {
  extern __shared__ char smem_raw[];
  __half2* Bsh = (__half2*)smem_raw;  // [64 pair-rows][BS_LD2]
  char* Abase = smem_raw + B_BYTES;   // 2 x (A fp32 64-row tile | C stage)
  const int tid = threadIdx.x;
  const int nh = blockIdx.x & 1;  // 0: top cols (0:128), 1: bot cols (128:256)

  // A tile async load: 2048 x 16B fp32 chunks, 8 per thread. 64 rows.
  auto issueA = [&](int tile, int buf) {
    char* dst = Abase + buf * A_BYTES;
    int row0 = tile * 64;
#pragma unroll
    for (int j = 0; j < 8; j++) {
      int s = tid + 256 * j;
      int r = s >> 5;
      int c4 = s & 31;
      int grow = row0 + r;
      const float* src = (grow < NN) ? (zp + (size_t)grow * 128)
                                     : (zo + (size_t)(grow - NN) * 128);
      cp16(dst + r * (AS_LDF * 4) + c4 * 16, src + c4 * 4);
    }
  };

  int t = blockIdx.x >> 1;  // 0..147
  issueA(t, 0);
  asm volatile("cp.async.commit_group;" ::: "memory");

  // One-time B fill for this N-half: Bsh[p][c] = (w1[2p+nh*128][c], w1[2p+1+nh*128][c])
  {
    const float4* w4 = (const float4*)w1;
#pragma unroll
    for (int j = 0; j < 8; j++) {
      int slot = tid + 256 * j;  // 2048 slots = 64 pairs x 32 col-quads
      int p = slot >> 5;
      int c4 = slot & 31;
      float4 fa = w4[(2 * p + nh * 128) * 32 + c4];
      float4 fb = w4[(2 * p + 1 + nh * 128) * 32 + c4];
      uint4 v;
      v.x = pack_h2(fa.x, fb.x);
      v.y = pack_h2(fa.y, fb.y);
      v.z = pack_h2(fa.z, fb.z);
      v.w = pack_h2(fa.w, fb.w);
      *(uint4*)((char*)Bsh + p * (BS_LD2 * 4) + c4 * 16) = v;
    }
  }

  const int lane = tid & 31;
  const int wid = tid >> 5;
  const int g = lane >> 2;
  const int tg = lane & 3;
  const int wm = wid & 1;   // 2 warp-rows of 32
  const int wn = wid >> 1;  // 4 warp-cols of 32
  const int arow = wm * 32;
  const int bcol = wn * 32;
  int buf = 0;

  while (true) {
    int tn = t + 148;
    bool more = (tn < MT64);
    if (more) issueA(tn, buf ^ 1);
    asm volatile("cp.async.commit_group;" ::: "memory");
    asm volatile("cp.async.wait_group 1;" ::: "memory");
    __syncthreads();

    const float* A = (const float*)(Abase + buf * A_BYTES);
    float acc[2][4][4];
#pragma unroll
    for (int mi = 0; mi < 2; mi++)
#pragma unroll
      for (int ni = 0; ni < 4; ni++)
#pragma unroll
        for (int q = 0; q < 4; q++) acc[mi][ni][q] = 0.f;

#pragma unroll
    for (int k0 = 0; k0 < 128; k0 += 16) {
      int hp = k0 >> 1;
      uint32_t bf[4][2];
#pragma unroll
      for (int ni = 0; ni < 4; ni++) {
        int col = bcol + ni * 8 + g;
        bf[ni][0] = *(const uint32_t*)&Bsh[(hp + tg) * BS_LD2 + col];
        bf[ni][1] = *(const uint32_t*)&Bsh[(hp + 4 + tg) * BS_LD2 + col];
      }
#pragma unroll
      for (int mi = 0; mi < 2; mi++) {
        int rb = arow + mi * 16 + g;
        uint32_t af[4];
        {
          float2 v = *(const float2*)&A[rb * AS_LDF + k0 + 2 * tg];
          af[0] = pack_h2(v.x, v.y);
        }
        {
          float2 v = *(const float2*)&A[(rb + 8) * AS_LDF + k0 + 2 * tg];
          af[1] = pack_h2(v.x, v.y);
        }
        {
          float2 v = *(const float2*)&A[rb * AS_LDF + k0 + 8 + 2 * tg];
          af[2] = pack_h2(v.x, v.y);
        }
        {
          float2 v = *(const float2*)&A[(rb + 8) * AS_LDF + k0 + 8 + 2 * tg];
          af[3] = pack_h2(v.x, v.y);
        }
#pragma unroll
        for (int ni = 0; ni < 4; ni++) mma_f16(acc[mi][ni], af, bf[ni]);
      }
    }

    // Stage C half-tile (64 x 128 fp16) into this A buffer, then coalesced
    // 256B row stores into the table at column offset nh*128.
    __syncthreads();
    __half* Cs = (__half*)(Abase + buf * A_BYTES);
#pragma unroll
    for (int mi = 0; mi < 2; mi++) {
#pragma unroll
      for (int hf = 0; hf < 2; hf++) {
        int r = wm * 32 + mi * 16 + hf * 8 + g;
#pragma unroll
        for (int ni = 0; ni < 4; ni++) {
          int c = bcol + ni * 8 + tg * 2;
          float v0 = acc[mi][ni][hf * 2];
          float v1 = acc[mi][ni][hf * 2 + 1];
          if (nh) {
            float2 bb = *(const float2*)(b1 + c);
            v0 += bb.x;
            v1 += bb.y;
          }
          *(__half2*)(Cs + r * CS_LDH + c) = __floats2half2_rn(v0, v1);
        }
      }
    }
    __syncthreads();
    int row0 = t * 64;
#pragma unroll
    for (int j = 0; j < 4; j++) {
      int slot = tid + 256 * j;  // 64 rows x 16 uint4
      int r = slot >> 4;
      int c4 = slot & 15;
      int grow = row0 + r;
      uint4 v = *(const uint4*)(Cs + r * CS_LDH + c4 * 8);
      __half* tab = (grow < NN) ? (g_P + (size_t)grow * 256)
                                : (g_O + (size_t)(grow - NN) * 256);
      *(uint4*)(tab + nh * 128 + c4 * 8) = v;
    }
    __syncthreads();
    if (!more) break;
    t = tn;
    buf ^= 1;
  }
}

// ---------------------------------------------------------------------------
// Edge pass (R6 version): persistent warps, 2 edges per warp-iteration
// (16-lane halves), half2 math.
// out[e] = relu(tabS[src,0:128] + tabD[dst,128:256]) . w2 + b2
// ---------------------------------------------------------------------------
#define NPAIRS (3 * EE / 2)  // 750000
__global__ void __launch_bounds__(256) edge_kernel(
    const int* __restrict__ e0, const int* __restrict__ e1,
    const int* __restrict__ e2, const float* __restrict__ w2,
    const float* __restrict__ b2, float* __restrict__ out) {
  const int lane = threadIdx.x & 31;
  const int h = lane >> 4;
  const int l = lane & 15;
  const int warpId = (blockIdx.x * 256 + threadIdx.x) >> 5;
  const int W = gridDim.x * 8;

  // Per-lane second-layer weights (features l*8 .. l*8+7) in half2.
  const float4 wa = ((const float4*)w2)[l * 2];
  const float4 wb = ((const float4*)w2)[l * 2 + 1];
  const __half2 w01 = __floats2half2_rn(wa.x, wa.y);
  const __half2 w23 = __floats2half2_rn(wa.z, wa.w);
  const __half2 w45 = __floats2half2_rn(wb.x, wb.y);
  const __half2 w67 = __floats2half2_rn(wb.z, wb.w);
  const __half2 z2 = __float2half2_rn(0.f);
  const float b2v = b2[0];

#pragma unroll 2
  for (int p = warpId; p < NPAIRS; p += W) {
    int e = 2 * p + h;
    int t = (e >= EE) + (e >= 2 * EE);
    int ei = e - t * EE;
    const int* idx = (t == 0) ? e0 : (t == 1) ? e1 : e2;
    int s = idx[ei];
    int d = idx[EE + ei];
    const __half* srow = ((t == 0) ? g_P : g_O) + (unsigned)s * 256u;
    const __half* drow = ((t == 1) ? g_P : g_O) + (unsigned)d * 256u + 128u;

    uint4 sa = ((const uint4*)srow)[l];
    uint4 da = ((const uint4*)drow)[l];

    __half2 h0 = __hmax2(__hadd2(*(__half2*)&sa.x, *(__half2*)&da.x), z2);
    __half2 h1 = __hmax2(__hadd2(*(__half2*)&sa.y, *(__half2*)&da.y), z2);
    __half2 h2 = __hmax2(__hadd2(*(__half2*)&sa.z, *(__half2*)&da.z), z2);
    __half2 h3 = __hmax2(__hadd2(*(__half2*)&sa.w, *(__half2*)&da.w), z2);
    __half2 pa = __hfma2(h1, w23, __hmul2(h0, w01));
    __half2 pb = __hfma2(h3, w67, __hmul2(h2, w45));
    float2 fa = __half22float2(pa);
    float2 fb = __half22float2(pb);
    float acc = (fa.x + fa.y) + (fb.x + fb.y);
#pragma unroll
    for (int o = 8; o; o >>= 1) acc += __shfl_xor_sync(0xffffffffu, acc, o);
    if (l == 0) out[e] = acc + b2v;
  }
}

extern "C" void kernel_launch(void* const* d_in, const int* in_sizes, int n_in,
                              void* d_out, int out_size) {
  const float* zp = (const float*)d_in[0];
  const float* zo = (const float*)d_in[1];
  const int* e0 = (const int*)d_in[2];
  const int* e1 = (const int*)d_in[3];
  const int* e2 = (const int*)d_in[4];
  const float* w1 = (const float*)d_in[5];
  const float* b1 = (const float*)d_in[6];
  const float* w2 = (const float*)d_in[7];
  const float* b2 = (const float*)d_in[8];

  cudaFuncSetAttribute(gemm_kernel,
                       cudaFuncAttributeMaxDynamicSharedMemorySize, SMEM_TOTAL);
  gemm_kernel<<<296, 256, SMEM_TOTAL>>>(zp, zo, w1, b1);

  edge_kernel<<<148 * 8, 256>>>(e0, e1, e2, w2, b2, (float*)d_out);
}

// round 10
// speedup vs baseline: 1.3653x; 1.0504x over previous
#include <cuda_runtime.h>
#include <cuda_fp16.h>
#include <cstdint>
#include <cstddef>

#define NN 100000
#define EE 500000
#define MROWS 200000
#define MT64 3125  // 200000/64 exact

// Per-node first-layer tables in fp16 (102.4 MB -> mostly L2-resident).
// P[n, 0:128] = z_pnode[n] @ w1_top ; P[n, 128:256] = z_pnode[n] @ w1_bot + b1
__device__ __half g_P[(size_t)NN * 256];
__device__ __half g_O[(size_t)NN * 256];

__device__ __forceinline__ void mma_f16(float* d, const uint32_t* a,
                                        const uint32_t* b) {
  asm volatile(
      "mma.sync.aligned.m16n8k16.row.col.f32.f16.f16.f32 "
      "{%0,%1,%2,%3}, {%4,%5,%6,%7}, {%8,%9}, {%0,%1,%2,%3};"
      : "+f"(d[0]), "+f"(d[1]), "+f"(d[2]), "+f"(d[3])
      : "r"(a[0]), "r"(a[1]), "r"(a[2]), "r"(a[3]), "r"(b[0]), "r"(b[1]));
}

__device__ __forceinline__ void cp16(void* smem_dst, const void* gmem_src) {
  uint32_t s = (uint32_t)__cvta_generic_to_shared(smem_dst);
  asm volatile("cp.async.cg.shared.global [%0], [%1], 16;" ::"r"(s),
               "l"(gmem_src));
}

__device__ __forceinline__ uint32_t pack_h2(float lo, float hi) {
  __half2 h = __floats2half2_rn(lo, hi);
  return *(uint32_t*)&h;
}

#define BS_LD2 264  // half2 per B pair-row (1056B; %128==32B -> conflict-free)
#define AS_LDF 132  // fp32 per A row (528B; words%32==4 -> conflict-free)
#define B_BYTES (64 * BS_LD2 * 4)           // 67584
#define A_BYTES (64 * AS_LDF * 4)           // 33792 per buffer
#define SMEM_TOTAL (B_BYTES + 3 * A_BYTES)  // 168960

// ---------------------------------------------------------------------------
// Fused persistent fp16 GEMM: C[200000,256] = Z @ [w1_top | w1_bot] (+b1 bot).
// 148 CTAs x 256 threads. CTA tile 64 x 256; 3125 tiles; depth-3 cp.async
// pipeline on fp32 A (A read exactly once). fp16 B resident. Direct scatter
// epilogue. 8 warps, warp tile 32x64.
// ---------------------------------------------------------------------------
__global__ void __launch_bounds__(256, 1) gemm_kernel(
    const float* __restrict__ zp, const float* __restrict__ zo,
    const float* __restrict__ w1, const float* __restrict__ b1) {
  extern __shared__ char smem_raw[];
  __half2* Bsh = (__half2*)smem_raw;  // [64 pair-rows][BS_LD2]
  char* Abase = smem_raw + B_BYTES;   // 3 x [64][AS_LDF] fp32
  const int tid = threadIdx.x;

  // A tile async load: 2048 x 16B fp32 chunks (64 rows), 8 per thread.
  auto issueA = [&](int tile, int buf) {
    char* dst = Abase + buf * A_BYTES;
    int row0 = tile * 64;
#pragma unroll
    for (int j = 0; j < 8; j++) {
      int s = tid + 256 * j;
      int r = s >> 5;
      int c4 = s & 31;
      int grow = row0 + r;
      const float* src = (grow < NN) ? (zp + (size_t)grow * 128)
                                     : (zo + (size_t)(grow - NN) * 128);
      cp16(dst + r * (AS_LDF * 4) + c4 * 16, src + c4 * 4);
    }
  };

  // Prologue: 3 tiles in flight.
  {
    int t0 = blockIdx.x;
#pragma unroll
    for (int s = 0; s < 3; s++) {
      if (t0 + s * 148 < MT64) issueA(t0 + s * 148, s);
      asm volatile("cp.async.commit_group;" ::: "memory");
    }
  }

  // One-time B fill: fp32 w1 -> fp16 [pair p][nn], half2=(w1[2p+..][c], w1[2p+1+..][c])
  {
    const float4* w4 = (const float4*)w1;
#pragma unroll
    for (int j = 0; j < 16; j++) {
      int slot = tid + 256 * j;  // 4096 slots
      int c4 = slot & 31;
      int p = (slot >> 5) & 63;
      int hh = slot >> 11;  // 0: top cols, 1: bot cols
      float4 fa = w4[(2 * p + hh * 128) * 32 + c4];
      float4 fb = w4[(2 * p + 1 + hh * 128) * 32 + c4];
      uint4 v;
      v.x = pack_h2(fa.x, fb.x);
      v.y = pack_h2(fa.y, fb.y);
      v.z = pack_h2(fa.z, fb.z);
      v.w = pack_h2(fa.w, fb.w);
      *(uint4*)((char*)Bsh + p * (BS_LD2 * 4) + (hh * 128 + c4 * 4) * 4) = v;
    }
  }

  const int lane = tid & 31;
  const int wid = tid >> 5;
  const int g = lane >> 2;
  const int tg = lane & 3;
  const int wm = wid & 1;   // 2 warp-rows of 32
  const int wn = wid >> 1;  // 4 warp-cols of 64
  const int arow = wm * 32;
  const int bcol = wn * 64;
  const bool bot = (bcol >= 128);

  // Hoist per-thread b1 pairs (columns fixed across tiles).
  float2 bb[8];
  if (bot) {
#pragma unroll
    for (int ni = 0; ni < 8; ni++)
      bb[ni] = *(const float2*)(b1 + (bcol - 128) + ni * 8 + tg * 2);
  }

  int buf = 0;
  for (int t = blockIdx.x; t < MT64; t += 148) {
    asm volatile("cp.async.wait_group 2;" ::: "memory");
    __syncthreads();

    const float* A = (const float*)(Abase + buf * A_BYTES);
    float acc[2][8][4];
#pragma unroll
    for (int mi = 0; mi < 2; mi++)
#pragma unroll
      for (int ni = 0; ni < 8; ni++)
#pragma unroll
        for (int q = 0; q < 4; q++) acc[mi][ni][q] = 0.f;

#pragma unroll
    for (int k0 = 0; k0 < 128; k0 += 16) {
      int hp = k0 >> 1;
      uint32_t bf[8][2];
#pragma unroll
      for (int ni = 0; ni < 8; ni++) {
        int col = bcol + ni * 8 + g;
        bf[ni][0] = *(const uint32_t*)&Bsh[(hp + tg) * BS_LD2 + col];
        bf[ni][1] = *(const uint32_t*)&Bsh[(hp + 4 + tg) * BS_LD2 + col];
      }
#pragma unroll
      for (int mi = 0; mi < 2; mi++) {
        int rb = arow + mi * 16 + g;
        uint32_t af[4];
        {
          float2 v = *(const float2*)&A[rb * AS_LDF + k0 + 2 * tg];
          af[0] = pack_h2(v.x, v.y);
        }
        {
          float2 v = *(const float2*)&A[(rb + 8) * AS_LDF + k0 + 2 * tg];
          af[1] = pack_h2(v.x, v.y);
        }
        {
          float2 v = *(const float2*)&A[rb * AS_LDF + k0 + 8 + 2 * tg];
          af[2] = pack_h2(v.x, v.y);
        }
        {
          float2 v = *(const float2*)&A[(rb + 8) * AS_LDF + k0 + 8 + 2 * tg];
          af[3] = pack_h2(v.x, v.y);
        }
#pragma unroll
        for (int ni = 0; ni < 8; ni++) mma_f16(acc[mi][ni], af, bf[ni]);
      }
    }

    // Direct scatter epilogue (L2 merges adjacent half2 stores).
    int row0 = t * 64;
#pragma unroll
    for (int mi = 0; mi < 2; mi++) {
#pragma unroll
      for (int hf = 0; hf < 2; hf++) {
        int grow = row0 + wm * 32 + mi * 16 + hf * 8 + g;
        __half* tab = (grow < NN) ? (g_P + (size_t)grow * 256)
                                  : (g_O + (size_t)(grow - NN) * 256);
#pragma unroll
        for (int ni = 0; ni < 8; ni++) {
          int c = bcol + ni * 8 + tg * 2;
          float v0 = acc[mi][ni][hf * 2];
          float v1 = acc[mi][ni][hf * 2 + 1];
          if (bot) {
            v0 += bb[ni].x;
            v1 += bb[ni].y;
          }
          *(__half2*)(tab + c) = __floats2half2_rn(v0, v1);
        }
      }
    }

    __syncthreads();  // all warps done reading A[buf] before refill
    int tn = t + 3 * 148;
    if (tn < MT64) issueA(tn, buf);
    asm volatile("cp.async.commit_group;" ::: "memory");
    buf = buf + 1;
    if (buf == 3) buf = 0;
  }
}

// ---------------------------------------------------------------------------
// Edge pass: persistent warps, 4 edges per warp-iteration (8-lane groups),
// half2 math. out[e] = relu(tabS[src,0:128] + tabD[dst,128:256]) . w2 + b2
// ---------------------------------------------------------------------------
#define NQUADS (3 * EE / 4)  // 375000
__global__ void __launch_bounds__(256) edge_kernel(
    const int* __restrict__ e0, const int* __restrict__ e1,
    const int* __restrict__ e2, const float* __restrict__ w2,
    const float* __restrict__ b2, float* __restrict__ out) {
  const int lane = threadIdx.x & 31;
  const int q = lane >> 3;  // edge slot in quad (0..3)
  const int l = lane & 7;   // lane within 8-lane group
  const int warpId = (blockIdx.x * 256 + threadIdx.x) >> 5;
  const int W = gridDim.x * 8;

  // Per-lane second-layer weights: features l*16 .. l*16+15, as 8 half2.
  __half2 wv[8];
#pragma unroll
  for (int j = 0; j < 4; j++) {
    float4 v = ((const float4*)w2)[l * 4 + j];
    wv[j * 2] = __floats2half2_rn(v.x, v.y);
    wv[j * 2 + 1] = __floats2half2_rn(v.z, v.w);
  }
  const __half2 z2 = __float2half2_rn(0.f);
  const float b2v = b2[0];

#pragma unroll 2
  for (int p = warpId; p < NQUADS; p += W) {
    int e = 4 * p + q;  // EE%4==0 -> quads never straddle type boundaries
    int t = (e >= EE) + (e >= 2 * EE);
    int ei = e - t * EE;
    const int* idx = (t == 0) ? e0 : (t == 1) ? e1 : e2;
    int s = idx[ei];
    int d = idx[EE + ei];
    const __half* srow = ((t == 0) ? g_P : g_O) + (unsigned)s * 256u;
    const __half* drow = ((t == 1) ? g_P : g_O) + (unsigned)d * 256u + 128u;

    // This lane covers features l*16 .. l*16+15: two uint4 from each row.
    uint4 sa0 = ((const uint4*)srow)[2 * l];
    uint4 sa1 = ((const uint4*)srow)[2 * l + 1];
    uint4 da0 = ((const uint4*)drow)[2 * l];
    uint4 da1 = ((const uint4*)drow)[2 * l + 1];

    __half2 pa, pb;
    {
      __half2 h0 = __hmax2(__hadd2(*(__half2*)&sa0.x, *(__half2*)&da0.x), z2);
      __half2 h1 = __hmax2(__hadd2(*(__half2*)&sa0.y, *(__half2*)&da0.y), z2);
      __half2 h2 = __hmax2(__hadd2(*(__half2*)&sa0.z, *(__half2*)&da0.z), z2);
      __half2 h3 = __hmax2(__hadd2(*(__half2*)&sa0.w, *(__half2*)&da0.w), z2);
      pa = __hfma2(h1, wv[1], __hmul2(h0, wv[0]));
      pa = __hfma2(h2, wv[2], pa);
      pa = __hfma2(h3, wv[3], pa);
    }
    {
      __half2 h0 = __hmax2(__hadd2(*(__half2*)&sa1.x, *(__half2*)&da1.x), z2);
      __half2 h1 = __hmax2(__hadd2(*(__half2*)&sa1.y, *(__half2*)&da1.y), z2);
      __half2 h2 = __hmax2(__hadd2(*(__half2*)&sa1.z, *(__half2*)&da1.z), z2);
      __half2 h3 = __hmax2(__hadd2(*(__half2*)&sa1.w, *(__half2*)&da1.w), z2);
      pb = __hfma2(h1, wv[5], __hmul2(h0, wv[4]));
      pb = __hfma2(h2, wv[6], pb);
      pb = __hfma2(h3, wv[7], pb);
    }
    float2 fa = __half22float2(pa);
    float2 fb = __half22float2(pb);
    float acc = (fa.x + fa.y) + (fb.x + fb.y);
    // Reduce within the 8-lane group (offsets stay inside the group).
#pragma unroll
    for (int o = 4; o; o >>= 1) acc += __shfl_xor_sync(0xffffffffu, acc, o);
    if (l == 0) out[e] = acc + b2v;
  }
}

extern "C" void kernel_launch(void* const* d_in, const int* in_sizes, int n_in,
                              void* d_out, int out_size) {
  const float* zp = (const float*)d_in[0];
  const float* zo = (const float*)d_in[1];
  const int* e0 = (const int*)d_in[2];
  const int* e1 = (const int*)d_in[3];
  const int* e2 = (const int*)d_in[4];
  const float* w1 = (const float*)d_in[5];
  const float* b1 = (const float*)d_in[6];
  const float* w2 = (const float*)d_in[7];
  const float* b2 = (const float*)d_in[8];

  cudaFuncSetAttribute(gemm_kernel,
                       cudaFuncAttributeMaxDynamicSharedMemorySize, SMEM_TOTAL);
  gemm_kernel<<<148, 256, SMEM_TOTAL>>>(zp, zo, w1, b1);

  edge_kernel<<<148 * 8, 256>>>(e0, e1, e2, w2, b2, (float*)d_out);
}

// round 12
// speedup vs baseline: 1.5673x; 1.1479x over previous
#include <cuda_runtime.h>
#include <cuda_fp16.h>
#include <cstdint>
#include <cstddef>

#define NN 100000
#define EE 500000
#define MROWS 200000
#define MTILES 1563  // ceil(200000/128)

// Per-node first-layer tables in fp16 (102.4 MB -> mostly L2-resident).
// P[n, 0:128] = z_pnode[n] @ w1_top ; P[n, 128:256] = z_pnode[n] @ w1_bot + b1
__device__ __half g_P[(size_t)NN * 256];
__device__ __half g_O[(size_t)NN * 256];

__device__ __forceinline__ void mma_f16(float* d, const uint32_t* a,
                                        const uint32_t* b) {
  asm volatile(
      "mma.sync.aligned.m16n8k16.row.col.f32.f16.f16.f32 "
      "{%0,%1,%2,%3}, {%4,%5,%6,%7}, {%8,%9}, {%0,%1,%2,%3};"
      : "+f"(d[0]), "+f"(d[1]), "+f"(d[2]), "+f"(d[3])
      : "r"(a[0]), "r"(a[1]), "r"(a[2]), "r"(a[3]), "r"(b[0]), "r"(b[1]));
}

__device__ __forceinline__ void cp16(void* smem_dst, const void* gmem_src) {
  uint32_t s = (uint32_t)__cvta_generic_to_shared(smem_dst);
  asm volatile("cp.async.cg.shared.global [%0], [%1], 16;" ::"r"(s),
               "l"(gmem_src));
}

__device__ __forceinline__ uint32_t pack_h2(float lo, float hi) {
  __half2 h = __floats2half2_rn(lo, hi);
  return *(uint32_t*)&h;
}

#define BS_LD2 264  // half2 per B pair-row (1056B; %128==32B -> conflict-free)
#define AS_LDF 132  // fp32 per A row (528B; words%32==4 -> conflict-free)
#define CS_LDH 264  // halves per staged C row (528B) == A row bytes
#define B_BYTES (64 * BS_LD2 * 4)           // 67584
#define A_BYTES (128 * AS_LDF * 4)          // 67584 (== 128*CS_LDH*2)
#define SMEM_TOTAL (B_BYTES + 2 * A_BYTES)  // 202752

// ---------------------------------------------------------------------------
// Fused persistent fp16 GEMM (R6-proven): C[200000,256] = Z @ [w1t | w1b]
// (+b1 on bot). 148 CTAs x 256 threads; CTA tile 128x256; fp32 A double-
// buffered via cp.async; fp16 B resident; C staged in smem for coalesced
// row stores. 8 warps, warp tile 64x64.
// ---------------------------------------------------------------------------
__global__ void __launch_bounds__(256, 1) gemm_kernel(
    const float* __restrict__ zp, const float* __restrict__ zo,
    const float* __restrict__ w1, const float* __restrict__ b1) {
  extern __shared__ char smem_raw[];
  __half2* Bsh = (__half2*)smem_raw;  // [64 pair-rows][BS_LD2]
  char* Abase = smem_raw + B_BYTES;   // 2 x (A fp32 tile | C half stage)
  const int tid = threadIdx.x;

  // A tile async load: 4096 x 16B fp32 chunks, 16 per thread.
  auto issueA = [&](int tile, int buf) {
    char* dst = Abase + buf * A_BYTES;
    int row0 = tile * 128;
#pragma unroll
    for (int j = 0; j < 16; j++) {
      int s = tid + 256 * j;
      int r = s >> 5;
      int c4 = s & 31;
      int grow = row0 + r;
      if (grow > MROWS - 1) grow = MROWS - 1;
      const float* src = (grow < NN) ? (zp + (size_t)grow * 128)
                                     : (zo + (size_t)(grow - NN) * 128);
      cp16(dst + r * (AS_LDF * 4) + c4 * 16, src + c4 * 4);
    }
  };

  int t = blockIdx.x;
  issueA(t, 0);
  asm volatile("cp.async.commit_group;" ::: "memory");

  // One-time B fill: fp32 w1 -> fp16 [pair p][nn], half2=(w1[2p+..][c], w1[2p+1+..][c])
  {
    const float4* w4 = (const float4*)w1;
#pragma unroll
    for (int j = 0; j < 16; j++) {
      int slot = tid + 256 * j;  // 4096 slots
      int c4 = slot & 31;
      int p = (slot >> 5) & 63;
      int hh = slot >> 11;  // 0: top cols, 1: bot cols
      float4 fa = w4[(2 * p + hh * 128) * 32 + c4];
      float4 fb = w4[(2 * p + 1 + hh * 128) * 32 + c4];
      uint4 v;
      v.x = pack_h2(fa.x, fb.x);
      v.y = pack_h2(fa.y, fb.y);
      v.z = pack_h2(fa.z, fb.z);
      v.w = pack_h2(fa.w, fb.w);
      *(uint4*)((char*)Bsh + p * (BS_LD2 * 4) + (hh * 128 + c4 * 4) * 4) = v;
    }
  }

  const int lane = tid & 31;
  const int wid = tid >> 5;
  const int g = lane >> 2;
  const int tg = lane & 3;
  const int wm = wid & 1;
  const int wn = wid >> 1;
  const int arow = wm * 64;
  const int bcol = wn * 64;
  const bool bot = (bcol >= 128);

  // Hoist per-thread b1 pairs (columns fixed across tiles).
  float2 bb[8];
  if (bot) {
#pragma unroll
    for (int ni = 0; ni < 8; ni++)
      bb[ni] = *(const float2*)(b1 + (bcol - 128) + ni * 8 + tg * 2);
  }

  int buf = 0;
  while (true) {
    int tn = t + gridDim.x;
    bool more = (tn < MTILES);
    if (more) issueA(tn, buf ^ 1);
    asm volatile("cp.async.commit_group;" ::: "memory");
    asm volatile("cp.async.wait_group 1;" ::: "memory");
    __syncthreads();

    const float* A = (const float*)(Abase + buf * A_BYTES);
    float acc[4][8][4];
#pragma unroll
    for (int mi = 0; mi < 4; mi++)
#pragma unroll
      for (int ni = 0; ni < 8; ni++)
#pragma unroll
        for (int q = 0; q < 4; q++) acc[mi][ni][q] = 0.f;

#pragma unroll
    for (int k0 = 0; k0 < 128; k0 += 16) {
      int hp = k0 >> 1;
      uint32_t bf[8][2];
#pragma unroll
      for (int ni = 0; ni < 8; ni++) {
        int col = bcol + ni * 8 + g;
        bf[ni][0] = *(const uint32_t*)&Bsh[(hp + tg) * BS_LD2 + col];
        bf[ni][1] = *(const uint32_t*)&Bsh[(hp + 4 + tg) * BS_LD2 + col];
      }
#pragma unroll
      for (int mi = 0; mi < 4; mi++) {
        int rb = arow + mi * 16 + g;
        uint32_t af[4];
        {
          float2 v = *(const float2*)&A[rb * AS_LDF + k0 + 2 * tg];
          af[0] = pack_h2(v.x, v.y);
        }
        {
          float2 v = *(const float2*)&A[(rb + 8) * AS_LDF + k0 + 2 * tg];
          af[1] = pack_h2(v.x, v.y);
        }
        {
          float2 v = *(const float2*)&A[rb * AS_LDF + k0 + 8 + 2 * tg];
          af[2] = pack_h2(v.x, v.y);
        }
        {
          float2 v = *(const float2*)&A[(rb + 8) * AS_LDF + k0 + 8 + 2 * tg];
          af[3] = pack_h2(v.x, v.y);
        }
#pragma unroll
        for (int ni = 0; ni < 8; ni++) mma_f16(acc[mi][ni], af, bf[ni]);
      }
    }

    // Stage C into this A buffer (fully consumed), then coalesced row stores.
    __syncthreads();
    __half* Cs = (__half*)(Abase + buf * A_BYTES);
#pragma unroll
    for (int mi = 0; mi < 4; mi++) {
#pragma unroll
      for (int hf = 0; hf < 2; hf++) {
        int r = wm * 64 + mi * 16 + hf * 8 + g;
#pragma unroll
        for (int ni = 0; ni < 8; ni++) {
          int c = bcol + ni * 8 + tg * 2;
          float v0 = acc[mi][ni][hf * 2];
          float v1 = acc[mi][ni][hf * 2 + 1];
          if (bot) {
            v0 += bb[ni].x;
            v1 += bb[ni].y;
          }
          *(__half2*)(Cs + r * CS_LDH + c) = __floats2half2_rn(v0, v1);
        }
      }
    }
    __syncthreads();
    int row0 = t * 128;
#pragma unroll
    for (int j = 0; j < 16; j++) {
      int slot = tid + 256 * j;  // 128 rows x 32 uint4
      int r = slot >> 5;
      int c4 = slot & 31;
      int grow = row0 + r;
      if (grow < MROWS) {
        uint4 v = *(const uint4*)(Cs + r * CS_LDH + c4 * 8);
        __half* tab = (grow < NN) ? (g_P + (size_t)grow * 256)
                                  : (g_O + (size_t)(grow - NN) * 256);
        *(uint4*)(tab + c4 * 8) = v;
      }
    }
    __syncthreads();
    if (!more) break;
    t = tn;
    buf ^= 1;
  }
}

// ---------------------------------------------------------------------------
// Edge pass (R8 structure + index prefetch pipeline + __ldg gathers):
// persistent warps, 2 edges per warp-iteration (16-lane halves), half2 math.
// out[e] = relu(tabS[src,0:128] + tabD[dst,128:256]) . w2 + b2
// ---------------------------------------------------------------------------
#define NPAIRS (3 * EE / 2)  // 750000
__global__ void __launch_bounds__(256) edge_kernel(
    const int* __restrict__ e0, const int* __restrict__ e1,
    const int* __restrict__ e2, const float* __restrict__ w2,
    const float* __restrict__ b2, float* __restrict__ out) {
  const int lane = threadIdx.x & 31;
  const int h = lane >> 4;
  const int l = lane & 15;
  const int warpId = (blockIdx.x * 256 + threadIdx.x) >> 5;
  const int W = gridDim.x * 8;

  // Per-lane second-layer weights (features l*8 .. l*8+7) in half2.
  const float4 wa = ((const float4*)w2)[l * 2];
  const float4 wb = ((const float4*)w2)[l * 2 + 1];
  const __half2 w01 = __floats2half2_rn(wa.x, wa.y);
  const __half2 w23 = __floats2half2_rn(wa.z, wa.w);
  const __half2 w45 = __floats2half2_rn(wb.x, wb.y);
  const __half2 w67 = __floats2half2_rn(wb.z, wb.w);
  const __half2 z2 = __float2half2_rn(0.f);
  const float b2v = b2[0];

  // Index fetch for pair p (this half-warp's edge 2p+h).
  auto fetch_idx = [&](int p, int& s, int& d, int& t) {
    int e = 2 * p + h;
    t = (e >= EE) + (e >= 2 * EE);
    int ei = e - t * EE;
    const int* idx = (t == 0) ? e0 : (t == 1) ? e1 : e2;
    s = __ldg(idx + ei);
    d = __ldg(idx + EE + ei);
  };

  int p = warpId;
  if (p >= NPAIRS) return;
  int s, d, t;
  fetch_idx(p, s, d, t);

  while (true) {
    // Gathers for the current pair (in flight while next indices load).
    const __half* srow = ((t == 0) ? g_P : g_O) + (unsigned)s * 256u;
    const __half* drow = ((t == 1) ? g_P : g_O) + (unsigned)d * 256u + 128u;
    uint4 sa = __ldg((const uint4*)srow + l);
    uint4 da = __ldg((const uint4*)drow + l);
    int e = 2 * p + h;

    // Prefetch next iteration's indices.
    int np = p + W;
    bool more = (np < NPAIRS);
    int ns, nd, nt;
    if (more) fetch_idx(np, ns, nd, nt);

    __half2 h0 = __hmax2(__hadd2(*(__half2*)&sa.x, *(__half2*)&da.x), z2);
    __half2 h1 = __hmax2(__hadd2(*(__half2*)&sa.y, *(__half2*)&da.y), z2);
    __half2 h2 = __hmax2(__hadd2(*(__half2*)&sa.z, *(__half2*)&da.z), z2);
    __half2 h3 = __hmax2(__hadd2(*(__half2*)&sa.w, *(__half2*)&da.w), z2);
    __half2 pa = __hfma2(h1, w23, __hmul2(h0, w01));
    __half2 pb = __hfma2(h3, w67, __hmul2(h2, w45));
    float2 fa = __half22float2(pa);
    float2 fb = __half22float2(pb);
    float acc = (fa.x + fa.y) + (fb.x + fb.y);
#pragma unroll
    for (int o = 8; o; o >>= 1) acc += __shfl_xor_sync(0xffffffffu, acc, o);
    if (l == 0) out[e] = acc + b2v;

    if (!more) break;
    p = np;
    s = ns;
    d = nd;
    t = nt;
  }
}

extern "C" void kernel_launch(void* const* d_in, const int* in_sizes, int n_in,
                              void* d_out, int out_size) {
  const float* zp = (const float*)d_in[0];
  const float* zo = (const float*)d_in[1];
  const int* e0 = (const int*)d_in[2];
  const int* e1 = (const int*)d_in[3];
  const int* e2 = (const int*)d_in[4];
  const float* w1 = (const float*)d_in[5];
  const float* b1 = (const float*)d_in[6];
  const float* w2 = (const float*)d_in[7];
  const float* b2 = (const float*)d_in[8];

  cudaFuncSetAttribute(gemm_kernel,
                       cudaFuncAttributeMaxDynamicSharedMemorySize, SMEM_TOTAL);
  gemm_kernel<<<148, 256, SMEM_TOTAL>>>(zp, zo, w1, b1);

  edge_kernel<<<148 * 8, 256>>>(e0, e1, e2, w2, b2, (float*)d_out);
}